// round 14
// baseline (speedup 1.0000x reference)
#include <cuda_runtime.h>
#include <cuda_bf16.h>
#include <math.h>

// Problem constants (fixed by the reference)
#define Bz   64
#define Tz   512
#define Hz   128
#define G3   384      // 3*H
#define C2H  256      // 2*H

typedef unsigned long long ull;

// ---------- packed f32x2 helpers ----------
__device__ __forceinline__ ull ffma2(ull a, ull b, ull c) {
    ull d;
    asm("fma.rn.f32x2 %0, %1, %2, %3;" : "=l"(d) : "l"(a), "l"(b), "l"(c));
    return d;
}
__device__ __forceinline__ ull pk2(float x, float y) {
    ull r;
    asm("mov.b64 %0, {%1, %2};" : "=l"(r) : "f"(x), "f"(y));
    return r;
}
__device__ __forceinline__ float f2sum(ull v) {
    unsigned lo, hi;
    asm("mov.b64 {%0, %1}, %2;" : "=r"(lo), "=r"(hi) : "l"(v));
    return __uint_as_float(lo) + __uint_as_float(hi);
}
__device__ __forceinline__ float sigmf(float x) {
    return 1.f / (1.f + __expf(-x));
}

// ---------- scratch (device globals; no allocation allowed) ----------
__device__ float d_gx[2ull * Bz * Tz * G3];            // 100.7 MB
__device__ float d_Hout[(size_t)Bz * Tz * C2H];        // 33.6 MB
__device__ float d_scores[(size_t)Bz * Tz];            // 128 KB
__device__ float d_Wc[2][G3][Hz];                      // fused Wih@We
__device__ float d_bc[2][G3];                          // fused bias

// ============================================================
// Kernel P: Wc[d] = Wih_d @ We  (384x128 = 128x128 @ ... ),
//           bc[d] = Wih_d @ be + bih_d
// grid (384, 2); 128 threads, thread e computes Wc[g][e]
// ============================================================
__global__ void __launch_bounds__(128) kPre(
    const float* __restrict__ We, const float* __restrict__ be,
    const float* __restrict__ Wihf, const float* __restrict__ bihf,
    const float* __restrict__ Wihb, const float* __restrict__ bihb)
{
    int g   = blockIdx.x;
    int dir = blockIdx.y;
    int e   = threadIdx.x;
    const float* Wih = dir ? Wihb : Wihf;
    const float* bih = dir ? bihb : bihf;

    float acc = 0.f, bacc = 0.f;
#pragma unroll 8
    for (int h = 0; h < Hz; h++) {
        float wg = __ldg(&Wih[g * Hz + h]);
        acc  = fmaf(wg, We[h * Hz + e], acc);
        bacc = fmaf(wg, __ldg(&be[h]), bacc);
    }
    d_Wc[dir][g][e] = acc;
    if (e == 0) d_bc[dir][g] = bacc + bih[g];
}

// ============================================================
// Kernel B': gx_d[b,t,:] = Wc_d @ emb[X[b,t]] + bc_d   (valid t only)
// grid: (256, 2 dirs); 384 threads (one per gate row g)
// ============================================================
__global__ void __launch_bounds__(384) kGateFused(
    const int* __restrict__ X, const int* __restrict__ lens,
    const float* __restrict__ emb)
{
    extern __shared__ float e_sh[];            // 128 tokens * 128 = 64 KB
    __shared__ int wid_sh[128];

    int b   = blockIdx.x >> 2;
    int t0  = (blockIdx.x & 3) * 128;
    int dir = blockIdx.y;
    int len = lens[b];
    int cnt = len - t0;
    if (cnt <= 0) return;
    if (cnt > 128) cnt = 128;
    int cnt2 = (cnt + 1) & ~1;

    int tid = threadIdx.x;
    if (tid < 128) wid_sh[tid] = (tid < cnt) ? X[b * Tz + t0 + tid] : 0;
    __syncthreads();

    // gather embedding rows (zero-pad odd tail token)
    for (int idx = tid; idx < cnt2 * Hz; idx += 384) {
        int r = idx >> 7;
        e_sh[idx] = (r < cnt) ? emb[(size_t)wid_sh[r] * Hz + (idx & 127)] : 0.f;
    }

    // fused weight row g = tid, 128 floats -> 64 packed regs
    ull w[64];
    const ull* wp = reinterpret_cast<const ull*>(&d_Wc[dir][tid][0]);
#pragma unroll
    for (int i = 0; i < 64; i++) w[i] = wp[i];
    float bias = d_bc[dir][tid];
    __syncthreads();

    float* outp = d_gx + ((size_t)dir * Bz * Tz + (size_t)b * Tz + t0) * G3;
    for (int tok = 0; tok < cnt; tok += 2) {
        const float4* x0 = reinterpret_cast<const float4*>(e_sh + tok * Hz);
        const float4* x1 = x0 + (Hz / 4);
        ull a0 = 0, a1 = 0, a2 = 0, a3 = 0;
#pragma unroll
        for (int i = 0; i < 32; i++) {
            float4 u = x0[i], v = x1[i];
            a0 = ffma2(w[2*i],   pk2(u.x, u.y), a0);
            a1 = ffma2(w[2*i+1], pk2(u.z, u.w), a1);
            a2 = ffma2(w[2*i],   pk2(v.x, v.y), a2);
            a3 = ffma2(w[2*i+1], pk2(v.z, v.w), a3);
        }
        outp[(size_t)tok * G3 + tid] = f2sum(a0) + f2sum(a1) + bias;
        if (tok + 1 < cnt)
            outp[(size_t)(tok + 1) * G3 + tid] = f2sum(a2) + f2sum(a3) + bias;
    }
}

// ============================================================
// Kernel C: GRU scan, one CTA per (b, dir). 384 threads.
// Forward: t = 0..len-1.  Backward: t = len-1..0 (padded steps never touch h).
// ============================================================
__global__ void __launch_bounds__(384) kScan(
    const int* __restrict__ lens,
    const float* __restrict__ Whf, const float* __restrict__ bhf,
    const float* __restrict__ Whb, const float* __restrict__ bhb)
{
    __shared__ __align__(16) float h_sh[Hz];
    __shared__ float gh_sh[G3];

    int b   = blockIdx.x;
    int dir = blockIdx.y;
    int len = lens[b];
    int tid = threadIdx.x;

    const float* Whh = dir ? Whb : Whf;
    const float* bhh = dir ? bhb : bhf;

    ull w[64];
    const ull* wp = reinterpret_cast<const ull*>(Whh + (size_t)tid * Hz);
#pragma unroll
    for (int i = 0; i < 64; i++) w[i] = wp[i];

    float bhr = 0.f, bhz = 0.f, bhn = 0.f;
    if (tid < Hz) {
        bhr = bhh[tid];
        bhz = bhh[Hz + tid];
        bhn = bhh[2 * Hz + tid];
        h_sh[tid] = 0.f;
    }

    const float* gxp = d_gx + ((size_t)dir * Bz * Tz + (size_t)b * Tz) * G3;
    float*       hop = d_Hout + (size_t)b * Tz * C2H + (size_t)dir * Hz;

    for (int step = 0; step < len; ++step) {
        int t = dir ? (len - 1 - step) : step;
        __syncthreads();   // h_sh from previous combine visible

        // issue gx loads early (consumed after the matvec barrier)
        float gxr = 0.f, gxz = 0.f, gxn = 0.f;
        const float* g0 = gxp + (size_t)t * G3;
        if (tid < Hz) { gxr = g0[tid]; gxz = g0[Hz + tid]; gxn = g0[2 * Hz + tid]; }

        // gh[g] = h . Whh[g,:]
        const float4* h4 = reinterpret_cast<const float4*>(h_sh);
        ull a0 = 0, a1 = 0;
#pragma unroll
        for (int i = 0; i < 32; i++) {
            float4 v = h4[i];
            a0 = ffma2(w[2*i],   pk2(v.x, v.y), a0);
            a1 = ffma2(w[2*i+1], pk2(v.z, v.w), a1);
        }
        gh_sh[tid] = f2sum(a0) + f2sum(a1);
        __syncthreads();

        if (tid < Hz) {
            float r = sigmf(gxr + gh_sh[tid] + bhr);
            float z = sigmf(gxz + gh_sh[Hz + tid] + bhz);
            float n = tanhf(gxn + r * (gh_sh[2 * Hz + tid] + bhn));
            float hn = n + z * (h_sh[tid] - n);   // (1-z)*n + z*h
            h_sh[tid] = hn;
            hop[(size_t)t * C2H + tid] = hn;
        }
    }
}

// ============================================================
// Kernel D: scores[b,t] = u . tanh(W_h2o @ Hout[b,t] + b_h2o)   (valid t only)
// grid: 512 = 64 b * 8 tiles of 64 tokens; 256 threads = 128 o-rows x 2 k-halves
// Warp-independent mainloop: NO per-token __syncthreads. Each warp deposits
// its 16-o partial into wpart[tok][warp]; one cleanup pass sums them.
// ============================================================
__global__ void __launch_bounds__(256) kScore(
    const int* __restrict__ lens,
    const float* __restrict__ Wo, const float* __restrict__ bo,
    const float* __restrict__ uw)
{
    extern __shared__ float hsh[];             // 64 tokens * 256 = 64 KB
    __shared__ float wpart[64][8];

    int blk = blockIdx.x;
    int b   = blk >> 3;
    int t0  = (blk & 7) * 64;
    int len = lens[b];
    int cnt = len - t0;
    if (cnt <= 0) return;
    if (cnt > 64) cnt = 64;
    int cnt2 = (cnt + 1) & ~1;

    int tid  = threadIdx.x;
    int o    = tid >> 1;
    int half = tid & 1;
    int lane = tid & 31;
    int wid  = tid >> 5;

    ull w[64];
    const ull* wp = reinterpret_cast<const ull*>(Wo + (size_t)o * C2H + half * Hz);
#pragma unroll
    for (int i = 0; i < 64; i++) w[i] = wp[i];
    float bb = bo[o], uo = uw[o];

    const float* hin = d_Hout + ((size_t)b * Tz + t0) * C2H;
    for (int idx = tid; idx < cnt2 * C2H; idx += 256)
        hsh[idx] = (idx < cnt * C2H) ? hin[idx] : 0.f;
    __syncthreads();

    for (int tok = 0; tok < cnt; tok += 2) {
        const float4* x0 = reinterpret_cast<const float4*>(hsh + tok * C2H + half * Hz);
        const float4* x1 = x0 + (C2H / 4);      // next token, same half
        ull a0 = 0, a1 = 0, a2 = 0, a3 = 0;
#pragma unroll
        for (int i = 0; i < 32; i++) {
            float4 u = x0[i], v = x1[i];
            a0 = ffma2(w[2*i],   pk2(u.x, u.y), a0);
            a1 = ffma2(w[2*i+1], pk2(u.z, u.w), a1);
            a2 = ffma2(w[2*i],   pk2(v.x, v.y), a2);
            a3 = ffma2(w[2*i+1], pk2(v.z, v.w), a3);
        }
        float s0 = f2sum(a0) + f2sum(a1);
        float s1 = f2sum(a2) + f2sum(a3);
        s0 += __shfl_xor_sync(0xffffffffu, s0, 1);   // combine k-halves
        s1 += __shfl_xor_sync(0xffffffffu, s1, 1);
        float y0 = tanhf(s0 + bb) * uo;
        float y1 = tanhf(s1 + bb) * uo;
        if (half) { y0 = 0.f; y1 = 0.f; }            // count each o once
#pragma unroll
        for (int d = 2; d <= 16; d <<= 1) {
            y0 += __shfl_xor_sync(0xffffffffu, y0, d);
            y1 += __shfl_xor_sync(0xffffffffu, y1, d);
        }
        if (lane == 0) {
            wpart[tok][wid] = y0;
            if (tok + 1 < cnt) wpart[tok + 1][wid] = y1;
        }
    }
    __syncthreads();

    if (tid < cnt) {
        float tot = 0.f;
#pragma unroll
        for (int k = 0; k < 8; k++) tot += wpart[tid][k];
        d_scores[(size_t)b * Tz + t0 + tid] = tot;
    }
}

// ============================================================
// Kernel E: per-b softmax over valid t, pooled = sum_t alpha_t * Hout[b,t,:]
// grid: 64; 256 threads (one per output channel)
// ============================================================
__global__ void __launch_bounds__(256) kPool(
    const int* __restrict__ lens, float* __restrict__ out)
{
    __shared__ float ssh[Tz];
    __shared__ float red[8];
    __shared__ float sh_mx, sh_sum;

    int b   = blockIdx.x;
    int len = lens[b];
    int tid = threadIdx.x;

    float m = -1e30f;
    for (int t = tid; t < len; t += 256) {
        float v = d_scores[(size_t)b * Tz + t];
        ssh[t] = v;
        m = fmaxf(m, v);
    }
#pragma unroll
    for (int o = 16; o; o >>= 1) m = fmaxf(m, __shfl_xor_sync(0xffffffffu, m, o));
    if ((tid & 31) == 0) red[tid >> 5] = m;
    __syncthreads();
    if (tid == 0) {
        float mm = red[0];
#pragma unroll
        for (int k = 1; k < 8; k++) mm = fmaxf(mm, red[k]);
        sh_mx = mm;
    }
    __syncthreads();

    float mx = sh_mx, ls = 0.f;
    for (int t = tid; t < len; t += 256) {
        float e = __expf(ssh[t] - mx);
        ssh[t] = e;
        ls += e;
    }
#pragma unroll
    for (int o = 16; o; o >>= 1) ls += __shfl_xor_sync(0xffffffffu, ls, o);
    __syncthreads();                 // red reuse safe (prev read done)
    if ((tid & 31) == 0) red[tid >> 5] = ls;
    __syncthreads();
    if (tid == 0) {
        float s = 0.f;
#pragma unroll
        for (int k = 0; k < 8; k++) s += red[k];
        sh_sum = s;
    }
    __syncthreads();

    float inv = 1.f / sh_sum;
    const float* hp = d_Hout + (size_t)b * Tz * C2H + tid;
    float acc = 0.f;
#pragma unroll 4
    for (int t = 0; t < len; t++)
        acc += ssh[t] * hp[(size_t)t * C2H];
    out[b * C2H + tid] = acc * inv;
}

// ============================================================
extern "C" void kernel_launch(void* const* d_in, const int* in_sizes, int n_in,
                              void* d_out, int out_size)
{
    (void)in_sizes; (void)n_in; (void)out_size;
    const int*   X    = (const int*)d_in[0];
    const int*   lens = (const int*)d_in[1];
    // d_in[2] = batch_size scalar (unused; B fixed at 64)
    const float* emb  = (const float*)d_in[3];
    const float* We   = (const float*)d_in[4];
    const float* be   = (const float*)d_in[5];
    const float* Wihf = (const float*)d_in[6];
    const float* Whhf = (const float*)d_in[7];
    const float* bihf = (const float*)d_in[8];
    const float* bhhf = (const float*)d_in[9];
    const float* Wihb = (const float*)d_in[10];
    const float* Whhb = (const float*)d_in[11];
    const float* bihb = (const float*)d_in[12];
    const float* bhhb = (const float*)d_in[13];
    const float* Wo   = (const float*)d_in[14];
    const float* bo   = (const float*)d_in[15];
    const float* uw   = (const float*)d_in[16];
    float* out = (float*)d_out;

    cudaFuncSetAttribute(kGateFused, cudaFuncAttributeMaxDynamicSharedMemorySize, 65536);
    cudaFuncSetAttribute(kScore,     cudaFuncAttributeMaxDynamicSharedMemorySize, 65536);

    kPre      <<<dim3(384, 2), 128>>>(We, be, Wihf, bihf, Wihb, bihb);
    kGateFused<<<dim3(256, 2), 384, 65536>>>(X, lens, emb);
    kScan     <<<dim3(64, 2), 384>>>(lens, Whhf, bhhf, Whhb, bhhb);
    kScore    <<<512, 256, 65536>>>(lens, Wo, bo, uw);
    kPool     <<<64, 256>>>(lens, out);
}

// round 15
// speedup vs baseline: 1.0107x; 1.0107x over previous
#include <cuda_runtime.h>
#include <cuda_bf16.h>
#include <math.h>

// Problem constants (fixed by the reference)
#define Bz   64
#define Tz   512
#define Hz   128
#define G3   384      // 3*H
#define C2H  256      // 2*H

typedef unsigned long long ull;

// ---------- packed f32x2 helpers ----------
__device__ __forceinline__ ull ffma2(ull a, ull b, ull c) {
    ull d;
    asm("fma.rn.f32x2 %0, %1, %2, %3;" : "=l"(d) : "l"(a), "l"(b), "l"(c));
    return d;
}
__device__ __forceinline__ ull pk2(float x, float y) {
    ull r;
    asm("mov.b64 %0, {%1, %2};" : "=l"(r) : "f"(x), "f"(y));
    return r;
}
__device__ __forceinline__ float f2sum(ull v) {
    unsigned lo, hi;
    asm("mov.b64 {%0, %1}, %2;" : "=r"(lo), "=r"(hi) : "l"(v));
    return __uint_as_float(lo) + __uint_as_float(hi);
}
__device__ __forceinline__ float sigmf(float x) {
    return 1.f / (1.f + __expf(-x));
}

// ---------- scratch (device globals; no allocation allowed) ----------
__device__ float d_gx[2ull * Bz * Tz * G3];            // 100.7 MB
__device__ float d_Hout[(size_t)Bz * Tz * C2H];        // 33.6 MB
__device__ float d_scores[(size_t)Bz * Tz];            // 128 KB
__device__ float d_Wc[2][G3][Hz];                      // fused Wih@We
__device__ float d_bc[2][G3];                          // fused bias

// ============================================================
// Kernel P: Wc[d] = Wih_d @ We  (384x128 = 128x128 @ ... ),
//           bc[d] = Wih_d @ be + bih_d
// grid (384, 2); 128 threads, thread e computes Wc[g][e]
// ============================================================
__global__ void __launch_bounds__(128) kPre(
    const float* __restrict__ We, const float* __restrict__ be,
    const float* __restrict__ Wihf, const float* __restrict__ bihf,
    const float* __restrict__ Wihb, const float* __restrict__ bihb)
{
    int g   = blockIdx.x;
    int dir = blockIdx.y;
    int e   = threadIdx.x;
    const float* Wih = dir ? Wihb : Wihf;
    const float* bih = dir ? bihb : bihf;

    float acc = 0.f, bacc = 0.f;
#pragma unroll 8
    for (int h = 0; h < Hz; h++) {
        float wg = __ldg(&Wih[g * Hz + h]);
        acc  = fmaf(wg, We[h * Hz + e], acc);
        bacc = fmaf(wg, __ldg(&be[h]), bacc);
    }
    d_Wc[dir][g][e] = acc;
    if (e == 0) d_bc[dir][g] = bacc + bih[g];
}

// ============================================================
// Kernel B': gx_d[b,t,:] = Wc_d @ emb[X[b,t]] + bc_d   (valid t only)
// grid: (256, 2 dirs); 384 threads (one per gate row g)
// ============================================================
__global__ void __launch_bounds__(384) kGateFused(
    const int* __restrict__ X, const int* __restrict__ lens,
    const float* __restrict__ emb)
{
    extern __shared__ float e_sh[];            // 128 tokens * 128 = 64 KB
    __shared__ int wid_sh[128];

    int b   = blockIdx.x >> 2;
    int t0  = (blockIdx.x & 3) * 128;
    int dir = blockIdx.y;
    int len = lens[b];
    int cnt = len - t0;
    if (cnt <= 0) return;
    if (cnt > 128) cnt = 128;
    int cnt2 = (cnt + 1) & ~1;

    int tid = threadIdx.x;
    if (tid < 128) wid_sh[tid] = (tid < cnt) ? X[b * Tz + t0 + tid] : 0;
    __syncthreads();

    // gather embedding rows (zero-pad odd tail token)
    for (int idx = tid; idx < cnt2 * Hz; idx += 384) {
        int r = idx >> 7;
        e_sh[idx] = (r < cnt) ? emb[(size_t)wid_sh[r] * Hz + (idx & 127)] : 0.f;
    }

    // fused weight row g = tid, 128 floats -> 64 packed regs
    ull w[64];
    const ull* wp = reinterpret_cast<const ull*>(&d_Wc[dir][tid][0]);
#pragma unroll
    for (int i = 0; i < 64; i++) w[i] = wp[i];
    float bias = d_bc[dir][tid];
    __syncthreads();

    float* outp = d_gx + ((size_t)dir * Bz * Tz + (size_t)b * Tz + t0) * G3;
    for (int tok = 0; tok < cnt; tok += 2) {
        const float4* x0 = reinterpret_cast<const float4*>(e_sh + tok * Hz);
        const float4* x1 = x0 + (Hz / 4);
        ull a0 = 0, a1 = 0, a2 = 0, a3 = 0;
#pragma unroll
        for (int i = 0; i < 32; i++) {
            float4 u = x0[i], v = x1[i];
            a0 = ffma2(w[2*i],   pk2(u.x, u.y), a0);
            a1 = ffma2(w[2*i+1], pk2(u.z, u.w), a1);
            a2 = ffma2(w[2*i],   pk2(v.x, v.y), a2);
            a3 = ffma2(w[2*i+1], pk2(v.z, v.w), a3);
        }
        outp[(size_t)tok * G3 + tid] = f2sum(a0) + f2sum(a1) + bias;
        if (tok + 1 < cnt)
            outp[(size_t)(tok + 1) * G3 + tid] = f2sum(a2) + f2sum(a3) + bias;
    }
}

// ============================================================
// Kernel C: GRU scan, one CTA per (b, dir). 384 threads.
// Forward: t = 0..len-1.  Backward: t = len-1..0 (padded steps never touch h).
// ============================================================
__global__ void __launch_bounds__(384) kScan(
    const int* __restrict__ lens,
    const float* __restrict__ Whf, const float* __restrict__ bhf,
    const float* __restrict__ Whb, const float* __restrict__ bhb)
{
    __shared__ __align__(16) float h_sh[Hz];
    __shared__ float gh_sh[G3];

    int b   = blockIdx.x;
    int dir = blockIdx.y;
    int len = lens[b];
    int tid = threadIdx.x;

    const float* Whh = dir ? Whb : Whf;
    const float* bhh = dir ? bhb : bhf;

    ull w[64];
    const ull* wp = reinterpret_cast<const ull*>(Whh + (size_t)tid * Hz);
#pragma unroll
    for (int i = 0; i < 64; i++) w[i] = wp[i];

    float bhr = 0.f, bhz = 0.f, bhn = 0.f;
    if (tid < Hz) {
        bhr = bhh[tid];
        bhz = bhh[Hz + tid];
        bhn = bhh[2 * Hz + tid];
        h_sh[tid] = 0.f;
    }

    const float* gxp = d_gx + ((size_t)dir * Bz * Tz + (size_t)b * Tz) * G3;
    float*       hop = d_Hout + (size_t)b * Tz * C2H + (size_t)dir * Hz;

    for (int step = 0; step < len; ++step) {
        int t = dir ? (len - 1 - step) : step;
        __syncthreads();   // h_sh from previous combine visible

        // issue gx loads early (consumed after the matvec barrier)
        float gxr = 0.f, gxz = 0.f, gxn = 0.f;
        const float* g0 = gxp + (size_t)t * G3;
        if (tid < Hz) { gxr = g0[tid]; gxz = g0[Hz + tid]; gxn = g0[2 * Hz + tid]; }

        // gh[g] = h . Whh[g,:]
        const float4* h4 = reinterpret_cast<const float4*>(h_sh);
        ull a0 = 0, a1 = 0;
#pragma unroll
        for (int i = 0; i < 32; i++) {
            float4 v = h4[i];
            a0 = ffma2(w[2*i],   pk2(v.x, v.y), a0);
            a1 = ffma2(w[2*i+1], pk2(v.z, v.w), a1);
        }
        gh_sh[tid] = f2sum(a0) + f2sum(a1);
        __syncthreads();

        if (tid < Hz) {
            float r = sigmf(gxr + gh_sh[tid] + bhr);
            float z = sigmf(gxz + gh_sh[Hz + tid] + bhz);
            float n = tanhf(gxn + r * (gh_sh[2 * Hz + tid] + bhn));
            float hn = n + z * (h_sh[tid] - n);   // (1-z)*n + z*h
            h_sh[tid] = hn;
            hop[(size_t)t * C2H + tid] = hn;
        }
    }
}

// ============================================================
// Kernel D: scores[b,t] = u . tanh(W_h2o @ Hout[b,t] + b_h2o)   (valid t only)
// grid: 512 = 64 b * 8 tiles of 64 tokens; 256 threads = 128 o-rows x 2 k-halves
// Warp-independent mainloop: NO per-token __syncthreads. Each warp deposits
// its 16-o partial into wpart[tok][warp]; one cleanup pass sums them.
// ============================================================
__global__ void __launch_bounds__(256) kScore(
    const int* __restrict__ lens,
    const float* __restrict__ Wo, const float* __restrict__ bo,
    const float* __restrict__ uw)
{
    extern __shared__ float hsh[];             // 64 tokens * 256 = 64 KB
    __shared__ float wpart[64][8];

    int blk = blockIdx.x;
    int b   = blk >> 3;
    int t0  = (blk & 7) * 64;
    int len = lens[b];
    int cnt = len - t0;
    if (cnt <= 0) return;
    if (cnt > 64) cnt = 64;
    int cnt2 = (cnt + 1) & ~1;

    int tid  = threadIdx.x;
    int o    = tid >> 1;
    int half = tid & 1;
    int lane = tid & 31;
    int wid  = tid >> 5;

    ull w[64];
    const ull* wp = reinterpret_cast<const ull*>(Wo + (size_t)o * C2H + half * Hz);
#pragma unroll
    for (int i = 0; i < 64; i++) w[i] = wp[i];
    float bb = bo[o], uo = uw[o];

    const float* hin = d_Hout + ((size_t)b * Tz + t0) * C2H;
    for (int idx = tid; idx < cnt2 * C2H; idx += 256)
        hsh[idx] = (idx < cnt * C2H) ? hin[idx] : 0.f;
    __syncthreads();

    for (int tok = 0; tok < cnt; tok += 2) {
        const float4* x0 = reinterpret_cast<const float4*>(hsh + tok * C2H + half * Hz);
        const float4* x1 = x0 + (C2H / 4);      // next token, same half
        ull a0 = 0, a1 = 0, a2 = 0, a3 = 0;
#pragma unroll
        for (int i = 0; i < 32; i++) {
            float4 u = x0[i], v = x1[i];
            a0 = ffma2(w[2*i],   pk2(u.x, u.y), a0);
            a1 = ffma2(w[2*i+1], pk2(u.z, u.w), a1);
            a2 = ffma2(w[2*i],   pk2(v.x, v.y), a2);
            a3 = ffma2(w[2*i+1], pk2(v.z, v.w), a3);
        }
        float s0 = f2sum(a0) + f2sum(a1);
        float s1 = f2sum(a2) + f2sum(a3);
        s0 += __shfl_xor_sync(0xffffffffu, s0, 1);   // combine k-halves
        s1 += __shfl_xor_sync(0xffffffffu, s1, 1);
        float y0 = tanhf(s0 + bb) * uo;
        float y1 = tanhf(s1 + bb) * uo;
        if (half) { y0 = 0.f; y1 = 0.f; }            // count each o once
#pragma unroll
        for (int d = 2; d <= 16; d <<= 1) {
            y0 += __shfl_xor_sync(0xffffffffu, y0, d);
            y1 += __shfl_xor_sync(0xffffffffu, y1, d);
        }
        if (lane == 0) {
            wpart[tok][wid] = y0;
            if (tok + 1 < cnt) wpart[tok + 1][wid] = y1;
        }
    }
    __syncthreads();

    if (tid < cnt) {
        float tot = 0.f;
#pragma unroll
        for (int k = 0; k < 8; k++) tot += wpart[tid][k];
        d_scores[(size_t)b * Tz + t0 + tid] = tot;
    }
}

// ============================================================
// Kernel E: per-b softmax over valid t, pooled = sum_t alpha_t * Hout[b,t,:]
// grid: 64; 256 threads (one per output channel)
// ============================================================
__global__ void __launch_bounds__(256) kPool(
    const int* __restrict__ lens, float* __restrict__ out)
{
    __shared__ float ssh[Tz];
    __shared__ float red[8];
    __shared__ float sh_mx, sh_sum;

    int b   = blockIdx.x;
    int len = lens[b];
    int tid = threadIdx.x;

    float m = -1e30f;
    for (int t = tid; t < len; t += 256) {
        float v = d_scores[(size_t)b * Tz + t];
        ssh[t] = v;
        m = fmaxf(m, v);
    }
#pragma unroll
    for (int o = 16; o; o >>= 1) m = fmaxf(m, __shfl_xor_sync(0xffffffffu, m, o));
    if ((tid & 31) == 0) red[tid >> 5] = m;
    __syncthreads();
    if (tid == 0) {
        float mm = red[0];
#pragma unroll
        for (int k = 1; k < 8; k++) mm = fmaxf(mm, red[k]);
        sh_mx = mm;
    }
    __syncthreads();

    float mx = sh_mx, ls = 0.f;
    for (int t = tid; t < len; t += 256) {
        float e = __expf(ssh[t] - mx);
        ssh[t] = e;
        ls += e;
    }
#pragma unroll
    for (int o = 16; o; o >>= 1) ls += __shfl_xor_sync(0xffffffffu, ls, o);
    __syncthreads();                 // red reuse safe (prev read done)
    if ((tid & 31) == 0) red[tid >> 5] = ls;
    __syncthreads();
    if (tid == 0) {
        float s = 0.f;
#pragma unroll
        for (int k = 0; k < 8; k++) s += red[k];
        sh_sum = s;
    }
    __syncthreads();

    float inv = 1.f / sh_sum;
    const float* hp = d_Hout + (size_t)b * Tz * C2H + tid;
    float acc = 0.f;
#pragma unroll 4
    for (int t = 0; t < len; t++)
        acc += ssh[t] * hp[(size_t)t * C2H];
    out[b * C2H + tid] = acc * inv;
}

// ============================================================
extern "C" void kernel_launch(void* const* d_in, const int* in_sizes, int n_in,
                              void* d_out, int out_size)
{
    (void)in_sizes; (void)n_in; (void)out_size;
    const int*   X    = (const int*)d_in[0];
    const int*   lens = (const int*)d_in[1];
    // d_in[2] = batch_size scalar (unused; B fixed at 64)
    const float* emb  = (const float*)d_in[3];
    const float* We   = (const float*)d_in[4];
    const float* be   = (const float*)d_in[5];
    const float* Wihf = (const float*)d_in[6];
    const float* Whhf = (const float*)d_in[7];
    const float* bihf = (const float*)d_in[8];
    const float* bhhf = (const float*)d_in[9];
    const float* Wihb = (const float*)d_in[10];
    const float* Whhb = (const float*)d_in[11];
    const float* bihb = (const float*)d_in[12];
    const float* bhhb = (const float*)d_in[13];
    const float* Wo   = (const float*)d_in[14];
    const float* bo   = (const float*)d_in[15];
    const float* uw   = (const float*)d_in[16];
    float* out = (float*)d_out;

    cudaFuncSetAttribute(kGateFused, cudaFuncAttributeMaxDynamicSharedMemorySize, 65536);
    cudaFuncSetAttribute(kScore,     cudaFuncAttributeMaxDynamicSharedMemorySize, 65536);

    kPre      <<<dim3(384, 2), 128>>>(We, be, Wihf, bihf, Wihb, bihb);
    kGateFused<<<dim3(256, 2), 384, 65536>>>(X, lens, emb);
    kScan     <<<dim3(64, 2), 384>>>(lens, Whhf, bhhf, Whhb, bhhb);
    kScore    <<<512, 256, 65536>>>(lens, Wo, bo, uw);
    kPool     <<<64, 256>>>(lens, out);
}